// round 4
// baseline (speedup 1.0000x reference)
#include <cuda_runtime.h>
#include <cuda_bf16.h>

// PositionEmbeddingSine — warp-centric, 2 rows / warp-iteration, STG.128.
// Output row (192 f32): [sin(q_x,p0),cos(q_x,p0),...,sin(q_x,p31),cos(q_x,p31), y..., z...]
//   q_{d,p} = val_d * 2pi/((s_d-1)+eps) * 10000^(-p/32)
// Lane owns freq pairs p0=2*(lane&15), p1=p0+1 → 4 contiguous floats → one float4 store.
// 3 rounds per row-pair cover all 96 float4 chunks with full-lane utilization.

#define SCALE_2PI 6.283185307179586f
#define EPS_F 1e-6f
#define L2T32 (13.287712379549449f / 32.0f)   // log2(10000)/32

__device__ int g_batch_start[4096];

__global__ void pes_starts_kernel(const int4* __restrict__ coords, int M) {
    int m = blockIdx.x * blockDim.x + threadIdx.x;
    if (m >= M) return;
    int b = __ldg(&coords[m].x);
    int prev = __shfl_up_sync(0xffffffffu, b, 1);
    if ((threadIdx.x & 31) == 0 && m > 0) prev = __ldg(&coords[m - 1].x);
    if (m == 0 || prev != b) {
        if (b >= 0 && b < 4096) g_batch_start[b] = m;
    }
}

__global__ void __launch_bounds__(256) pes_main_kernel(
    const int4* __restrict__ coords,   // [M] rows: (b, x, y, z)
    const int* __restrict__ psx,
    const int* __restrict__ psy,
    const int* __restrict__ psz,
    const int* __restrict__ pml,
    float* __restrict__ out,
    int M)
{
    const int lane = threadIdx.x & 31;
    const int k16  = lane & 15;
    const bool hi  = lane >= 16;
    const int warp = (blockIdx.x * blockDim.x + threadIdx.x) >> 5;
    const int nw   = (gridDim.x * blockDim.x) >> 5;

    const int max_len = __ldg(pml);

    const float gx = SCALE_2PI / ((float)(__ldg(psx) - 1) + EPS_F);
    const float gy = SCALE_2PI / ((float)(__ldg(psy) - 1) + EPS_F);
    const float gz = SCALE_2PI / ((float)(__ldg(psz) - 1) + EPS_F);

    // This lane's two frequency scales (loop-invariant in every round).
    const float invA = exp2f(-(float)(2 * k16)     * L2T32);
    const float invB = exp2f(-(float)(2 * k16 + 1) * L2T32);

    for (int m0 = warp * 2; m0 < M; m0 += nw * 2) {
        const int  m1 = m0 + 1;
        const bool v1 = (m1 < M);

        int4 c0 = __ldg(&coords[m0]);
        int4 c1 = v1 ? __ldg(&coords[m1]) : c0;

        float* r0 = out + ((long long)c0.x * max_len + (m0 - g_batch_start[c0.x])) * 192;
        float* r1 = out + ((long long)c1.x * max_len + (m1 - g_batch_start[c1.x])) * 192;

        // Per-round scaled coordinate value for this lane.
        float a0 = hi ? (float)c0.z * gy : (float)c0.y * gx;   // row0: dims x|y
        float a1 = hi ? (float)c1.y * gx : (float)c0.w * gz;   // row0 z | row1 x
        float a2 = hi ? (float)c1.w * gz : (float)c1.z * gy;   // row1: dims y|z

        float s0a, c0a, s0b, c0b;
        float s1a, c1a, s1b, c1b;
        float s2a, c2a, s2b, c2b;
        __sincosf(a0 * invA, &s0a, &c0a);  __sincosf(a0 * invB, &s0b, &c0b);
        __sincosf(a1 * invA, &s1a, &c1a);  __sincosf(a1 * invB, &s1b, &c1b);
        __sincosf(a2 * invA, &s2a, &c2a);  __sincosf(a2 * invB, &s2b, &c2b);

        // Round 0: row0 floats [0,128)          chunk = lane
        *(float4*)(r0 + 4 * lane) = make_float4(s0a, c0a, s0b, c0b);
        // Round 1: row0 floats [128,192) (lanes<16) | row1 floats [0,64) (lanes>=16)
        if (!hi) {
            *(float4*)(r0 + 128 + 4 * k16) = make_float4(s1a, c1a, s1b, c1b);
        } else if (v1) {
            *(float4*)(r1 + 4 * k16) = make_float4(s1a, c1a, s1b, c1b);
        }
        // Round 2: row1 floats [64,192)         chunk = 16 + lane
        if (v1) {
            *(float4*)(r1 + 64 + 4 * lane) = make_float4(s2a, c2a, s2b, c2b);
        }
    }
}

extern "C" void kernel_launch(void* const* d_in, const int* in_sizes, int n_in,
                              void* d_out, int out_size)
{
    const int* coords = (const int*)d_in[0];
    const int* psx    = (const int*)d_in[1];
    const int* psy    = (const int*)d_in[2];
    const int* psz    = (const int*)d_in[3];
    // d_in[4] = n_batches (unused: batch ids come from coords)
    const int* pml    = (const int*)d_in[5];
    float* out        = (float*)d_out;

    int M = in_sizes[0] / 4;

    {
        int threads = 256;
        int blocks = (M + threads - 1) / threads;
        pes_starts_kernel<<<blocks, threads>>>((const int4*)coords, M);
    }
    {
        int threads = 256;
        int blocks = 148 * 8;
        pes_main_kernel<<<blocks, threads>>>((const int4*)coords, psx, psy, psz, pml, out, M);
    }
}